// round 9
// baseline (speedup 1.0000x reference)
#include <cuda_runtime.h>
#include <cuda_bf16.h>
#include <cuda_fp16.h>
#include <cstdint>
#include <cstddef>

#define SQ   2048
#define BB   2
#define NH   12
#define DH   64
#define EM   768
#define MROWS (BB*SQ)      /* 4096 */
#define NBH  (BB*NH)       /* 24   */

/* ------------- scratch (device globals, allocation-free) ------------- */
__device__ __align__(16) __nv_bfloat16 g_Ahi[4ull*MROWS*EM];
__device__ __align__(16) __nv_bfloat16 g_Alo[4ull*MROWS*EM];
__device__ __align__(16) __nv_bfloat16 g_Wthi[5ull*EM*EM];
__device__ __align__(16) __nv_bfloat16 g_Wtlo[5ull*EM*EM];
__device__ __align__(16) __nv_bfloat16 g_Qhi[(size_t)NBH*SQ*DH];
__device__ __align__(16) __nv_bfloat16 g_Qlo[(size_t)NBH*SQ*DH];
__device__ __align__(16) __nv_bfloat16 g_Khi[(size_t)NBH*SQ*DH];
__device__ __align__(16) __nv_bfloat16 g_Klo[(size_t)NBH*SQ*DH];
__device__ __align__(16) __half        g_Vthi[(size_t)NBH*DH*SQ];  /* fp16 */
__device__ __align__(16) __half        g_Vtlo[(size_t)NBH*DH*SQ];
__device__ __align__(16) __nv_bfloat16 g_Ohi[(size_t)MROWS*EM];
__device__ __align__(16) __nv_bfloat16 g_Olo[(size_t)MROWS*EM];
__device__ float g_e [(size_t)NBH*SQ*SQ];
__device__ float g_lp[(size_t)NBH*SQ*32];
__device__ float g_main[(size_t)MROWS*EM];

/* ============================ helpers ============================ */
__device__ __forceinline__ void split2(float x, float y, uint32_t& h, uint32_t& l) {
    __nv_bfloat162 hv = __floats2bfloat162_rn(x, y);
    float rx = x - __bfloat162float(__low2bfloat16(hv));
    float ry = y - __bfloat162float(__high2bfloat16(hv));
    __nv_bfloat162 lv = __floats2bfloat162_rn(rx, ry);
    h = *reinterpret_cast<uint32_t*>(&hv);
    l = *reinterpret_cast<uint32_t*>(&lv);
}
__device__ __forceinline__ void split2h(float x, float y, uint32_t& h, uint32_t& l) {
    __half2 hv = __floats2half2_rn(x, y);
    float rx = x - __half2float(__low2half(hv));
    float ry = y - __half2float(__high2half(hv));
    __half2 lv = __floats2half2_rn(rx, ry);
    h = *reinterpret_cast<uint32_t*>(&hv);
    l = *reinterpret_cast<uint32_t*>(&lv);
}

__device__ __forceinline__ void mma_bf16(float* d, const uint32_t* a, const uint32_t* b) {
    asm volatile(
        "mma.sync.aligned.m16n8k16.row.col.f32.bf16.bf16.f32 "
        "{%0,%1,%2,%3}, {%4,%5,%6,%7}, {%8,%9}, {%0,%1,%2,%3};"
        : "+f"(d[0]), "+f"(d[1]), "+f"(d[2]), "+f"(d[3])
        : "r"(a[0]), "r"(a[1]), "r"(a[2]), "r"(a[3]), "r"(b[0]), "r"(b[1]));
}
__device__ __forceinline__ void mma_fp16(float* d, const uint32_t* a, const uint32_t* b) {
    asm volatile(
        "mma.sync.aligned.m16n8k16.row.col.f32.f16.f16.f32 "
        "{%0,%1,%2,%3}, {%4,%5,%6,%7}, {%8,%9}, {%0,%1,%2,%3};"
        : "+f"(d[0]), "+f"(d[1]), "+f"(d[2]), "+f"(d[3])
        : "r"(a[0]), "r"(a[1]), "r"(a[2]), "r"(a[3]), "r"(b[0]), "r"(b[1]));
}

#define LDMX4(r, a)                                                          \
    asm volatile("ldmatrix.sync.aligned.m8n8.x4.shared.b16 {%0,%1,%2,%3}, [%4];" \
        : "=r"((r)[0]), "=r"((r)[1]), "=r"((r)[2]), "=r"((r)[3]) : "r"(a))

__device__ __forceinline__ void cp16(uint32_t dst, const void* src) {
    asm volatile("cp.async.cg.shared.global [%0], [%1], 16;" :: "r"(dst), "l"(src));
}
#define CP_COMMIT() asm volatile("cp.async.commit_group;" ::: "memory")
#define CP_WAIT0()  asm volatile("cp.async.wait_group 0;" ::: "memory")
#define CP_WAIT1()  asm volatile("cp.async.wait_group 1;" ::: "memory")

__device__ __forceinline__ uint32_t smem_u32(const void* p) {
    return (uint32_t)__cvta_generic_to_shared(const_cast<void*>(p));
}

/* 3xBF16 split tile: warp computes (MT*16)m x (NT*8)n over KC k16-groups */
template<int MT, int NT, int RB, int KC>
__device__ __forceinline__ void compute_tile(
    float acc[][4], uint32_t Ah, uint32_t Al, uint32_t Bh, uint32_t Bl,
    int wm, int wn, int lid)
{
    const int arow = lid & 15;
    const int ak   = (lid >> 4) * 16;
    const int brow = (lid & 7) + ((lid >> 4) & 1) * 8;
    const int bk   = ((lid >> 3) & 1) * 16;
#pragma unroll
    for (int kc = 0; kc < KC; ++kc) {
        uint32_t aH[MT][4], aL[MT][4];
#pragma unroll
        for (int mt = 0; mt < MT; ++mt) {
            uint32_t off = (uint32_t)(wm * (MT * 16) + mt * 16 + arow) * RB + kc * 32 + ak;
            LDMX4(aH[mt], Ah + off);
            LDMX4(aL[mt], Al + off);
        }
#pragma unroll
        for (int np = 0; np < NT / 2; ++np) {
            uint32_t boff = (uint32_t)(wn * (NT * 8) + np * 16 + brow) * RB + kc * 32 + bk;
            uint32_t bH[4], bL[4];
            LDMX4(bH, Bh + boff);
            LDMX4(bL, Bl + boff);
#pragma unroll
            for (int half = 0; half < 2; ++half) {
                int nt = np * 2 + half;
                uint32_t* bh = bH + half * 2;
                uint32_t* bl = bL + half * 2;
#pragma unroll
                for (int mt = 0; mt < MT; ++mt) {
                    mma_bf16(acc[mt * NT + nt], aH[mt], bh);
                    mma_bf16(acc[mt * NT + nt], aH[mt], bl);
                    mma_bf16(acc[mt * NT + nt], aL[mt], bh);
                }
            }
        }
    }
}

/* 2xFP16 tile: A single fp16, B fp16 hi/lo */
template<int MT, int NT, int RB, int KC>
__device__ __forceinline__ void compute_tile_h(
    float acc[][4], uint32_t A, uint32_t Bh, uint32_t Bl,
    int wm, int wn, int lid)
{
    const int arow = lid & 15;
    const int ak   = (lid >> 4) * 16;
    const int brow = (lid & 7) + ((lid >> 4) & 1) * 8;
    const int bk   = ((lid >> 3) & 1) * 16;
#pragma unroll
    for (int kc = 0; kc < KC; ++kc) {
        uint32_t aH[MT][4];
#pragma unroll
        for (int mt = 0; mt < MT; ++mt) {
            uint32_t off = (uint32_t)(wm * (MT * 16) + mt * 16 + arow) * RB + kc * 32 + ak;
            LDMX4(aH[mt], A + off);
        }
#pragma unroll
        for (int np = 0; np < NT / 2; ++np) {
            uint32_t boff = (uint32_t)(wn * (NT * 8) + np * 16 + brow) * RB + kc * 32 + bk;
            uint32_t bH[4], bL[4];
            LDMX4(bH, Bh + boff);
            LDMX4(bL, Bl + boff);
#pragma unroll
            for (int half = 0; half < 2; ++half) {
                int nt = np * 2 + half;
#pragma unroll
                for (int mt = 0; mt < MT; ++mt) {
                    mma_fp16(acc[mt * NT + nt], aH[mt], bH + half * 2);
                    mma_fp16(acc[mt * NT + nt], aH[mt], bL + half * 2);
                }
            }
        }
    }
}

/* ============================================================
 * split_inputs / transpose_w  (prep)
 * ============================================================ */
__global__ __launch_bounds__(256) void split_inputs(
    const float* q, const float* k, const float* kg, const float* v,
    __nv_bfloat16* hi, __nv_bfloat16* lo)
{
    const float* S;
    if (blockIdx.y == 0) S = q; else if (blockIdx.y == 1) S = k;
    else if (blockIdx.y == 2) S = kg; else S = v;
    size_t off = (size_t)blockIdx.y * MROWS * EM;
    size_t i = (size_t)blockIdx.x * 256 + threadIdx.x;
    float4 x = ((const float4*)S)[i];
    uint32_t h0, l0, h1, l1;
    split2(x.x, x.y, h0, l0);
    split2(x.z, x.w, h1, l1);
    *(uint2*)(hi + off + i * 4) = make_uint2(h0, h1);
    *(uint2*)(lo + off + i * 4) = make_uint2(l0, l1);
}

__global__ __launch_bounds__(256) void transpose_w(
    const float* W0, const float* W1, const float* W2,
    const float* W3, const float* W4,
    __nv_bfloat16* outhi, __nv_bfloat16* outlo)
{
    const float* W;
    if (blockIdx.z == 0) W = W0; else if (blockIdx.z == 1) W = W1;
    else if (blockIdx.z == 2) W = W2; else if (blockIdx.z == 3) W = W3; else W = W4;
    size_t off = (size_t)blockIdx.z * EM * EM;
    __shared__ float t[32][33];
    int tx = threadIdx.x, ty = threadIdx.y;
    int x = blockIdx.x * 32 + tx;
    int y0 = blockIdx.y * 32;
    for (int i = ty; i < 32; i += 8)
        t[i][tx] = W[(size_t)(y0 + i) * EM + x];
    __syncthreads();
    int xo = blockIdx.y * 32 + tx;
    int yo0 = blockIdx.x * 32;
    for (int i = ty; i < 32; i += 8) {
        float val = t[tx][i];
        __nv_bfloat16 h = __float2bfloat16(val);
        float r = val - __bfloat162float(h);
        size_t idx = off + (size_t)(yo0 + i) * EM + xo;
        outhi[idx] = h;
        outlo[idx] = __float2bfloat16(r);
    }
}

/* ============================================================
 * proj_body: BM=64, BN=128, BK=32; 2-stage cp.async pipeline
 * stage layout: [Ah 5120][Al 5120][Bh 10240][Bl 10240] = 30720
 * mode 0: fp32 [m,n]; 1: bf16 hi/lo [bh,s,d]; 2: FP16 hi/lo [bh,d,s]
 * ============================================================ */
#define PJ_STGB 30720

__device__ __forceinline__ void proj_body(
    uint32_t* smw,
    const __nv_bfloat16* A1h, const __nv_bfloat16* A1l,
    const __nv_bfloat16* A2h, const __nv_bfloat16* A2l,
    const __nv_bfloat16* W1h, const __nv_bfloat16* W1l,
    const __nv_bfloat16* W2h, const __nv_bfloat16* W2l,
    const float* b1, const float* b2,
    float* outf, void* outhi, void* outlo,
    int mode, int n0, int m0)
{
    const int tid = threadIdx.x, wid = tid >> 5, lid = tid & 31;
    const int wm = wid & 1, wn = wid >> 1, grp = lid >> 2, tig = lid & 3;
    const uint32_t smb = smem_u32(smw);
    const int LDB = EM * 2;

    float acc[8][4];
#pragma unroll
    for (int i = 0; i < 8; ++i)
#pragma unroll
        for (int j = 0; j < 4; ++j) acc[i][j] = 0.f;

    const int CPP = EM / 32;
    const int NCH = (A2h ? 2 : 1) * CPP;

    auto issue = [&](int slot, int c) {
        int pass = (c >= CPP);
        int k0b = (c - pass * CPP) * 64;
        const char* sAh = (const char*)(pass ? A2h : A1h) + (size_t)m0 * LDB;
        const char* sAl = (const char*)(pass ? A2l : A1l) + (size_t)m0 * LDB;
        const char* sWh = (const char*)(pass ? W2h : W1h) + (size_t)n0 * LDB;
        const char* sWl = (const char*)(pass ? W2l : W1l) + (size_t)n0 * LDB;
        uint32_t base = smb + (uint32_t)slot * PJ_STGB;
#pragma unroll
        for (int it = 0; it < 6; ++it) {
            int t = tid + it * 256;
            const char* sp;
            uint32_t doff;
            int row, seg;
            if (t < 512) {
                int buf = t >> 8, e = t & 255;
                row = e >> 2; seg = e & 3;
                sp = buf ? sAl : sAh;
                doff = (uint32_t)buf * 5120 + row * 80 + seg * 16;
            } else {
                int e = t - 512;
                int buf = e >> 9; e &= 511;
                row = e >> 2; seg = e & 3;
                sp = buf ? sWl : sWh;
                doff = 10240u + (uint32_t)buf * 10240 + row * 80 + seg * 16;
            }
            cp16(base + doff, sp + (size_t)row * LDB + k0b + seg * 16);
        }
    };

    issue(0, 0); CP_COMMIT();
    issue(1, 1); CP_COMMIT();
    for (int c = 0; c < NCH; ++c) {
        CP_WAIT1();
        __syncthreads();
        uint32_t cb = smb + (uint32_t)(c & 1) * PJ_STGB;
        compute_tile<2, 4, 80, 2>(acc, cb, cb + 5120, cb + 10240, cb + 20480,
                                  wm, wn, lid);
        __syncthreads();
        if (c + 2 < NCH) issue(c & 1, c + 2);
        CP_COMMIT();
    }

    float* Csm = (float*)smw;
    const int CS = 132;
#pragma unroll
    for (int mt = 0; mt < 2; ++mt)
#pragma unroll
        for (int nt = 0; nt < 4; ++nt) {
            int row = wm * 32 + mt * 16 + grp, col = wn * 32 + nt * 8 + tig * 2;
            float* a = acc[mt * 4 + nt];
            *(float2*)&Csm[row * CS + col]       = make_float2(a[0], a[1]);
            *(float2*)&Csm[(row + 8) * CS + col] = make_float2(a[2], a[3]);
        }
    __syncthreads();

    if (mode == 2) {
        int b = m0 >> 11, sbase = m0 & (SQ - 1);
#pragma unroll
        for (int it = 0; it < 8; ++it) {
            int e = tid + it * 256;
            int col = e >> 4, sb = e & 15;
            int nn = n0 + col;
            float bias = b1[nn];
            float4 v;
            v.x = Csm[(sb * 4 + 0) * CS + col] + bias;
            v.y = Csm[(sb * 4 + 1) * CS + col] + bias;
            v.z = Csm[(sb * 4 + 2) * CS + col] + bias;
            v.w = Csm[(sb * 4 + 3) * CS + col] + bias;
            int hh = nn >> 6, d = nn & 63;
            size_t idx = (((size_t)(b * NH + hh)) * DH + d) * SQ + sbase + sb * 4;
            uint32_t h0, l0, h1, l1;
            split2h(v.x, v.y, h0, l0);
            split2h(v.z, v.w, h1, l1);
            *(uint2*)((__half*)outhi + idx) = make_uint2(h0, h1);
            *(uint2*)((__half*)outlo + idx) = make_uint2(l0, l1);
        }
    } else {
#pragma unroll
        for (int it = 0; it < 8; ++it) {
            int e = tid + it * 256;
            int row = e >> 5, c4 = (e & 31) * 4;
            int m = m0 + row, n = n0 + c4;
            float4 v = *(float4*)&Csm[row * CS + c4];
            v.x += b1[n + 0]; v.y += b1[n + 1]; v.z += b1[n + 2]; v.w += b1[n + 3];
            if (b2) { v.x += b2[n + 0]; v.y += b2[n + 1]; v.z += b2[n + 2]; v.w += b2[n + 3]; }
            if (mode == 1) {
                int b = m >> 11, sA = m & (SQ - 1);
                int hh = n >> 6, d = n & 63;
                size_t idx = (((size_t)(b * NH + hh)) * SQ + sA) * DH + d;
                uint32_t h0, l0, h1, l1;
                split2(v.x, v.y, h0, l0);
                split2(v.z, v.w, h1, l1);
                *(uint2*)((__nv_bfloat16*)outhi + idx) = make_uint2(h0, h1);
                *(uint2*)((__nv_bfloat16*)outlo + idx) = make_uint2(l0, l1);
            } else {
                *(float4*)(outf + (size_t)m * EM + n) = v;
            }
        }
    }
}

__global__ __launch_bounds__(256, 3) void proj_qkv(
    const __nv_bfloat16* Ahi, const __nv_bfloat16* Alo,
    const __nv_bfloat16* Whi, const __nv_bfloat16* Wlo,
    const float* bq, const float* bk, const float* bkg, const float* bv,
    __nv_bfloat16* Qhi, __nv_bfloat16* Qlo,
    __nv_bfloat16* Khi, __nv_bfloat16* Klo,
    __half* Vthi, __half* Vtlo)
{
    extern __shared__ uint32_t smw[];
    const int n0 = blockIdx.x * 128, m0 = blockIdx.y * 64;
    const size_t AT = (size_t)MROWS * EM, WT = (size_t)EM * EM;
    if (blockIdx.z == 0)
        proj_body(smw, Ahi, Alo, nullptr, nullptr, Whi, Wlo, nullptr, nullptr,
                  bq, nullptr, nullptr, Qhi, Qlo, 1, n0, m0);
    else if (blockIdx.z == 1)
        proj_body(smw, Ahi + AT, Alo + AT, Ahi + 2*AT, Alo + 2*AT,
                  Whi + WT, Wlo + WT, Whi + 2*WT, Wlo + 2*WT,
                  bk, bkg, nullptr, Khi, Klo, 1, n0, m0);
    else
        proj_body(smw, Ahi + 3*AT, Alo + 3*AT, nullptr, nullptr,
                  Whi + 3*WT, Wlo + 3*WT, nullptr, nullptr,
                  bv, nullptr, nullptr, Vthi, Vtlo, 2, n0, m0);
}

__global__ __launch_bounds__(256, 3) void proj_o(
    const __nv_bfloat16* Ohi, const __nv_bfloat16* Olo,
    const __nv_bfloat16* Whi, const __nv_bfloat16* Wlo,
    const float* bo, float* C)
{
    extern __shared__ uint32_t smw[];
    const size_t WT = (size_t)EM * EM;
    proj_body(smw, Ohi, Olo, nullptr, nullptr, Whi + 4*WT, Wlo + 4*WT,
              nullptr, nullptr, bo, nullptr, C, nullptr, nullptr, 0,
              blockIdx.x * 128, blockIdx.y * 64);
}

/* ============================================================
 * qk_mma: BM=64, BN=64, K=64 single-shot, 4 CTAs/SM
 * smem: [Qh 9216][Ql 9216][Kh 9216][Kl 9216] = 36864
 * ============================================================ */
__global__ __launch_bounds__(256, 4) void qk_mma(
    const __nv_bfloat16* Qhi, const __nv_bfloat16* Qlo,
    const __nv_bfloat16* Khi, const __nv_bfloat16* Klo,
    const int* __restrict__ mask, float* __restrict__ e_out,
    float* __restrict__ lp)
{
    extern __shared__ uint32_t smw[];
    const int tid = threadIdx.x, wid = tid >> 5, lid = tid & 31;
    const int n0 = blockIdx.x * 64, m0 = blockIdx.y * 64;
    const int bh = blockIdx.z, b = bh / NH;
    const int wm = wid & 1, wn = wid >> 1, grp = lid >> 2, tig = lid & 3;
    const uint32_t smb = smem_u32(smw);
    const char* ptrs[4] = {
        (const char*)Qhi + ((size_t)bh * SQ + m0) * 128,
        (const char*)Qlo + ((size_t)bh * SQ + m0) * 128,
        (const char*)Khi + ((size_t)bh * SQ + n0) * 128,
        (const char*)Klo + ((size_t)bh * SQ + n0) * 128 };

#pragma unroll
    for (int it = 0; it < 8; ++it) {
        int t = tid + it * 256;
        int buf = t >> 9, e = t & 511;
        int row = e >> 3, seg = e & 7;
        cp16(smb + (uint32_t)buf * 9216 + row * 144 + seg * 16,
             ptrs[buf] + (size_t)row * 128 + seg * 16);
    }
    CP_COMMIT();
    CP_WAIT0();
    __syncthreads();

    float acc[4][4];
#pragma unroll
    for (int i = 0; i < 4; ++i)
#pragma unroll
        for (int j = 0; j < 4; ++j) acc[i][j] = 0.f;

    compute_tile<2, 2, 144, 4>(acc, smb, smb + 9216, smb + 18432, smb + 27648,
                               wm, wn, lid);
    __syncthreads();

    float* Csm = (float*)smw;
    const int CS = 68;
#pragma unroll
    for (int mt = 0; mt < 2; ++mt)
#pragma unroll
        for (int nt = 0; nt < 2; ++nt) {
            int row = wm * 32 + mt * 16 + grp, col = wn * 16 + nt * 8 + tig * 2;
            float* a = acc[mt * 2 + nt];
            *(float2*)&Csm[row * CS + col]       = make_float2(a[0], a[1]);
            *(float2*)&Csm[(row + 8) * CS + col] = make_float2(a[2], a[3]);
        }
    __syncthreads();

    const int* mb = mask + (size_t)b * SQ * SQ;
    float* eb = e_out + (size_t)bh * SQ * SQ;
#pragma unroll 1
    for (int it = 0; it < 4; ++it) {
        int eidx = tid + it * 256;
        int row = eidx >> 4, c4 = (eidx & 15) * 4;   /* 16 threads per row */
        int m = m0 + row, n = n0 + c4;
        float4 v = *(float4*)&Csm[row * CS + c4];
        int4 mk = *(const int4*)(mb + (size_t)m * SQ + n);
        v.x = mk.x ? __expf(v.x * 0.125f) : 0.f;
        v.y = mk.y ? __expf(v.y * 0.125f) : 0.f;
        v.z = mk.z ? __expf(v.z * 0.125f) : 0.f;
        v.w = mk.w ? __expf(v.w * 0.125f) : 0.f;
        *(float4*)(eb + (size_t)m * SQ + n) = v;
        float s4 = v.x + v.y + v.z + v.w;
#pragma unroll
        for (int o = 8; o; o >>= 1) s4 += __shfl_xor_sync(0xffffffffu, s4, o);
        if ((lid & 15) == 0)
            lp[((size_t)bh * SQ + m) * 32 + blockIdx.x] = s4;
    }
}

/* ============================================================
 * av_mma: BM=64, BN=64; P fp16 (1 word), V fp16 hi/lo; 2-MMA
 * stage: [P 5120][Vh 5120][Vl 5120] = 15360; x2 + invl 256
 * ============================================================ */
#define AV_STGB 15360

__global__ __launch_bounds__(256, 4) void av_mma(
    const float* __restrict__ e_in, const float* __restrict__ lp,
    const __half* Vhi, const __half* Vlo,
    float* __restrict__ attn, __nv_bfloat16* Ohi, __nv_bfloat16* Olo)
{
    extern __shared__ uint32_t smw[];
    const int tid = threadIdx.x, wid = tid >> 5, lid = tid & 31;
    const int m0 = blockIdx.x * 64;
    const int bh = blockIdx.y, b = bh / NH, hh = bh % NH;
    const int wm = wid & 1, wn = wid >> 1, grp = lid >> 2, tig = lid & 3;
    const uint32_t smb = smem_u32(smw);
    const float* Pb = e_in + (size_t)bh * SQ * SQ + (size_t)m0 * SQ;
    float* attnb = attn + (size_t)bh * SQ * SQ + (size_t)m0 * SQ;
    const char* Vh = (const char*)Vhi + (size_t)bh * DH * SQ * 2;
    const char* Vl = (const char*)Vlo + (size_t)bh * DH * SQ * 2;
    float* invl = (float*)((char*)smw + 2 * AV_STGB);

    if (tid < 64) {
        const float* q = lp + ((size_t)bh * SQ + m0 + tid) * 32;
        float s = 0.f;
#pragma unroll
        for (int i = 0; i < 32; ++i) s += q[i];
        invl[tid] = 1.f / fmaxf(s, 1e-30f);
    }
    __syncthreads();

    float acc[4][4];
#pragma unroll
    for (int i = 0; i < 4; ++i)
#pragma unroll
        for (int j = 0; j < 4; ++j) acc[i][j] = 0.f;

    const int vrow = tid >> 2, vseg = tid & 3;

    auto ldgP = [&](int k0, float4* v) {
#pragma unroll
        for (int p = 0; p < 2; ++p) {
            int i = tid + p * 256, r = i >> 3, c = i & 7;
            v[p] = *(const float4*)(Pb + (size_t)r * SQ + k0 + c * 4);
        }
    };
    /* normalize, write attn fp32, convert to fp16 into smem */
    auto stsP = [&](int slot, const float4* v, int k0) {
        char* H = (char*)smw + slot * AV_STGB;
#pragma unroll
        for (int p = 0; p < 2; ++p) {
            int i = tid + p * 256, r = i >> 3, c = i & 7;
            float il = invl[r];
            float4 w;
            w.x = v[p].x * il; w.y = v[p].y * il;
            w.z = v[p].z * il; w.w = v[p].w * il;
            *(float4*)(attnb + (size_t)r * SQ + k0 + c * 4) = w;
            __half2 h0 = __floats2half2_rn(w.x, w.y);
            __half2 h1 = __floats2half2_rn(w.z, w.w);
            *(uint2*)(H + r * 80 + c * 8) =
                make_uint2(*(uint32_t*)&h0, *(uint32_t*)&h1);
        }
    };
    auto ldgV = [&](int k0b, uint4& h, uint4& l) {
        size_t o = (size_t)vrow * (SQ * 2) + k0b + vseg * 16;
        h = *(const uint4*)(Vh + o);
        l = *(const uint4*)(Vl + o);
    };
    auto stsV = [&](int slot, uint4 vh, uint4 vl) {
        char* base = (char*)smw + slot * AV_STGB + 5120;
        *(uint4*)(base + vrow * 80 + vseg * 16) = vh;
        *(uint4*)(base + 5120 + vrow * 80 + vseg * 16) = vl;
    };

    float4 va[2];
    uint4 vh, vl;
    ldgP(0, va);
    ldgV(0, vh, vl);
    stsP(0, va, 0);
    stsV(0, vh, vl);
    __syncthreads();

    const int NCH = SQ / 32;
    for (int c = 0; c < NCH; ++c) {
        bool more = (c + 1 < NCH);
        if (more) {
            ldgP((c + 1) * 32, va);
            ldgV((c + 1) * 64, vh, vl);
        }
        uint32_t cb = smb + (uint32_t)(c & 1) * AV_STGB;
        compute_tile_h<2, 2, 80, 2>(acc, cb, cb + 5120, cb + 10240,
                                    wm, wn, lid);
        __syncthreads();
        if (more) {
            stsP((c + 1) & 1, va, (c + 1) * 32);
            stsV((c + 1) & 1, vh, vl);
        }
        __syncthreads();
    }

    float* Csm = (float*)smw;
    const int CS = 68;
#pragma unroll
    for (int mt = 0; mt < 2; ++mt)
#pragma unroll
        for (int nt = 0; nt < 2; ++nt) {
            int row = wm * 32 + mt * 16 + grp, col = wn * 16 + nt * 8 + tig * 2;
            float* a = acc[mt * 2 + nt];
            *(float2*)&Csm[row * CS + col]       = make_float2(a[0], a[1]);
            *(float2*)&Csm[(row + 8) * CS + col] = make_float2(a[2], a[3]);
        }
    __syncthreads();

#pragma unroll
    for (int it = 0; it < 4; ++it) {
        int e = tid + it * 256;
        int row = e >> 4, c4 = (e & 15) * 4;
        float4 v = *(float4*)&Csm[row * CS + c4];
        size_t idx = (size_t)(b * SQ + m0 + row) * EM + hh * DH + c4;
        uint32_t h0, l0, h1, l1;
        split2(v.x, v.y, h0, l0);
        split2(v.z, v.w, h1, l1);
        *(uint2*)(Ohi + idx) = make_uint2(h0, h1);
        *(uint2*)(Olo + idx) = make_uint2(l0, l1);
    }
}

/* ===================================================================== */
extern "C" void kernel_launch(void* const* d_in, const int* in_sizes, int n_in,
                              void* d_out, int out_size)
{
    (void)in_sizes; (void)n_in;
    const float* query = (const float*)d_in[0];
    const float* key   = (const float*)d_in[1];
    const float* value = (const float*)d_in[2];
    const float* kginf = (const float*)d_in[3];
    const int*   mask  = (const int*)d_in[4];
    const float* Wq  = (const float*)d_in[5];  const float* bq  = (const float*)d_in[6];
    const float* Wk  = (const float*)d_in[7];  const float* bk  = (const float*)d_in[8];
    const float* Wv  = (const float*)d_in[9];  const float* bv  = (const float*)d_in[10];
    const float* Wkg = (const float*)d_in[11]; const float* bkg = (const float*)d_in[12];
    const float* Wo  = (const float*)d_in[13]; const float* bo  = (const float*)d_in[14];

    __nv_bfloat16 *ahi, *alo, *whi, *wlo, *qhi, *qlo, *khi, *klo, *ohi, *olo;
    __half *vthi, *vtlo;
    float *ge, *glp, *gmain;
    cudaGetSymbolAddress((void**)&ahi,  g_Ahi);
    cudaGetSymbolAddress((void**)&alo,  g_Alo);
    cudaGetSymbolAddress((void**)&whi,  g_Wthi);
    cudaGetSymbolAddress((void**)&wlo,  g_Wtlo);
    cudaGetSymbolAddress((void**)&qhi,  g_Qhi);
    cudaGetSymbolAddress((void**)&qlo,  g_Qlo);
    cudaGetSymbolAddress((void**)&khi,  g_Khi);
    cudaGetSymbolAddress((void**)&klo,  g_Klo);
    cudaGetSymbolAddress((void**)&vthi, g_Vthi);
    cudaGetSymbolAddress((void**)&vtlo, g_Vtlo);
    cudaGetSymbolAddress((void**)&ohi,  g_Ohi);
    cudaGetSymbolAddress((void**)&olo,  g_Olo);
    cudaGetSymbolAddress((void**)&ge,   g_e);
    cudaGetSymbolAddress((void**)&glp,  g_lp);
    cudaGetSymbolAddress((void**)&gmain, g_main);

    const long long MAIN = (long long)MROWS * EM;
    const long long ATTN = (long long)NBH * SQ * SQ;
    float* out = (float*)d_out;
    float* main_out;
    float* attn;
    long long osz = (long long)out_size;
    if (osz >= MAIN + ATTN)      { main_out = out; attn = out + MAIN; }
    else if (osz >= ATTN)        { attn = out; main_out = gmain; }
    else                         { main_out = out; attn = ge; }

    const int PJ_SMEM = 2 * PJ_STGB;           /* 61440 */
    const int QK_SMEM = 36864;
    const int AV_SMEM = 2 * AV_STGB + 256;     /* 30976 */
    cudaFuncSetAttribute(proj_qkv, cudaFuncAttributeMaxDynamicSharedMemorySize, PJ_SMEM);
    cudaFuncSetAttribute(proj_o,   cudaFuncAttributeMaxDynamicSharedMemorySize, PJ_SMEM);
    cudaFuncSetAttribute(qk_mma,   cudaFuncAttributeMaxDynamicSharedMemorySize, QK_SMEM);
    cudaFuncSetAttribute(av_mma,   cudaFuncAttributeMaxDynamicSharedMemorySize, AV_SMEM);

    dim3 blk(256);
    split_inputs<<<dim3(MROWS * EM / 4 / 256, 4), blk>>>(query, key, kginf, value, ahi, alo);
    transpose_w<<<dim3(EM/32, EM/32, 5), dim3(32, 8)>>>(Wq, Wk, Wkg, Wv, Wo, whi, wlo);

    proj_qkv<<<dim3(EM/128, MROWS/64, 3), blk, PJ_SMEM>>>(
        ahi, alo, whi, wlo, bq, bk, bkg, bv, qhi, qlo, khi, klo, vthi, vtlo);

    qk_mma<<<dim3(SQ/64, SQ/64, NBH), blk, QK_SMEM>>>(
        qhi, qlo, khi, klo, mask, ge, glp);

    av_mma<<<dim3(SQ/64, NBH), blk, AV_SMEM>>>(
        ge, glp, vthi, vtlo, attn, ohi, olo);

    proj_o<<<dim3(EM/128, MROWS/64), blk, PJ_SMEM>>>(ohi, olo, whi, wlo, bo, main_out);
}

// round 10
// speedup vs baseline: 1.1145x; 1.1145x over previous
#include <cuda_runtime.h>
#include <cuda_bf16.h>
#include <cuda_fp16.h>
#include <cstdint>
#include <cstddef>

#define SQ   2048
#define BB   2
#define NH   12
#define DH   64
#define EM   768
#define MROWS (BB*SQ)      /* 4096 */
#define NBH  (BB*NH)       /* 24   */

/* ------------- scratch (device globals, allocation-free) ------------- */
__device__ __align__(16) __nv_bfloat16 g_Ahi[4ull*MROWS*EM];
__device__ __align__(16) __nv_bfloat16 g_Alo[4ull*MROWS*EM];
__device__ __align__(16) __nv_bfloat16 g_Wthi[5ull*EM*EM];
__device__ __align__(16) __nv_bfloat16 g_Wtlo[5ull*EM*EM];
__device__ __align__(16) __nv_bfloat16 g_Qhi[(size_t)NBH*SQ*DH];
__device__ __align__(16) __nv_bfloat16 g_Qlo[(size_t)NBH*SQ*DH];
__device__ __align__(16) __nv_bfloat16 g_Khi[(size_t)NBH*SQ*DH];
__device__ __align__(16) __nv_bfloat16 g_Klo[(size_t)NBH*SQ*DH];
__device__ __align__(16) __half        g_Vthi[(size_t)NBH*DH*SQ];
__device__ __align__(16) __half        g_Vtlo[(size_t)NBH*DH*SQ];
__device__ __align__(16) __nv_bfloat16 g_Ohi[(size_t)MROWS*EM];
__device__ __align__(16) __nv_bfloat16 g_Olo[(size_t)MROWS*EM];
__device__ __align__(16) __half g_e[(size_t)NBH*SQ*SQ];   /* fp16 unnorm exp */
__device__ float g_lp[(size_t)NBH*SQ*16];
__device__ float g_main[(size_t)MROWS*EM];
__device__ float g_attnf[(size_t)NBH*SQ*SQ];              /* attn fallback */

/* ============================ helpers ============================ */
__device__ __forceinline__ void split2(float x, float y, uint32_t& h, uint32_t& l) {
    __nv_bfloat162 hv = __floats2bfloat162_rn(x, y);
    float rx = x - __bfloat162float(__low2bfloat16(hv));
    float ry = y - __bfloat162float(__high2bfloat16(hv));
    __nv_bfloat162 lv = __floats2bfloat162_rn(rx, ry);
    h = *reinterpret_cast<uint32_t*>(&hv);
    l = *reinterpret_cast<uint32_t*>(&lv);
}
__device__ __forceinline__ void split2h(float x, float y, uint32_t& h, uint32_t& l) {
    __half2 hv = __floats2half2_rn(x, y);
    float rx = x - __half2float(__low2half(hv));
    float ry = y - __half2float(__high2half(hv));
    __half2 lv = __floats2half2_rn(rx, ry);
    h = *reinterpret_cast<uint32_t*>(&hv);
    l = *reinterpret_cast<uint32_t*>(&lv);
}

__device__ __forceinline__ void mma_bf16(float* d, const uint32_t* a, const uint32_t* b) {
    asm volatile(
        "mma.sync.aligned.m16n8k16.row.col.f32.bf16.bf16.f32 "
        "{%0,%1,%2,%3}, {%4,%5,%6,%7}, {%8,%9}, {%0,%1,%2,%3};"
        : "+f"(d[0]), "+f"(d[1]), "+f"(d[2]), "+f"(d[3])
        : "r"(a[0]), "r"(a[1]), "r"(a[2]), "r"(a[3]), "r"(b[0]), "r"(b[1]));
}
__device__ __forceinline__ void mma_fp16(float* d, const uint32_t* a, const uint32_t* b) {
    asm volatile(
        "mma.sync.aligned.m16n8k16.row.col.f32.f16.f16.f32 "
        "{%0,%1,%2,%3}, {%4,%5,%6,%7}, {%8,%9}, {%0,%1,%2,%3};"
        : "+f"(d[0]), "+f"(d[1]), "+f"(d[2]), "+f"(d[3])
        : "r"(a[0]), "r"(a[1]), "r"(a[2]), "r"(a[3]), "r"(b[0]), "r"(b[1]));
}

#define LDMX4(r, a)                                                          \
    asm volatile("ldmatrix.sync.aligned.m8n8.x4.shared.b16 {%0,%1,%2,%3}, [%4];" \
        : "=r"((r)[0]), "=r"((r)[1]), "=r"((r)[2]), "=r"((r)[3]) : "r"(a))

__device__ __forceinline__ void cp16(uint32_t dst, const void* src) {
    asm volatile("cp.async.cg.shared.global [%0], [%1], 16;" :: "r"(dst), "l"(src));
}
#define CP_COMMIT() asm volatile("cp.async.commit_group;" ::: "memory")
#define CP_WAIT0()  asm volatile("cp.async.wait_group 0;" ::: "memory")
#define CP_WAIT1()  asm volatile("cp.async.wait_group 1;" ::: "memory")

__device__ __forceinline__ uint32_t smem_u32(const void* p) {
    return (uint32_t)__cvta_generic_to_shared(const_cast<void*>(p));
}

/* 3xBF16 split tile: warp computes (MT*16)m x (NT*8)n over KC k16-groups */
template<int MT, int NT, int RB, int KC>
__device__ __forceinline__ void compute_tile(
    float acc[][4], uint32_t Ah, uint32_t Al, uint32_t Bh, uint32_t Bl,
    int wm, int wn, int lid)
{
    const int arow = lid & 15;
    const int ak   = (lid >> 4) * 16;
    const int brow = (lid & 7) + ((lid >> 4) & 1) * 8;
    const int bk   = ((lid >> 3) & 1) * 16;
#pragma unroll
    for (int kc = 0; kc < KC; ++kc) {
        uint32_t aH[MT][4], aL[MT][4];
#pragma unroll
        for (int mt = 0; mt < MT; ++mt) {
            uint32_t off = (uint32_t)(wm * (MT * 16) + mt * 16 + arow) * RB + kc * 32 + ak;
            LDMX4(aH[mt], Ah + off);
            LDMX4(aL[mt], Al + off);
        }
#pragma unroll
        for (int np = 0; np < NT / 2; ++np) {
            uint32_t boff = (uint32_t)(wn * (NT * 8) + np * 16 + brow) * RB + kc * 32 + bk;
            uint32_t bH[4], bL[4];
            LDMX4(bH, Bh + boff);
            LDMX4(bL, Bl + boff);
#pragma unroll
            for (int half = 0; half < 2; ++half) {
                int nt = np * 2 + half;
                uint32_t* bh = bH + half * 2;
                uint32_t* bl = bL + half * 2;
#pragma unroll
                for (int mt = 0; mt < MT; ++mt) {
                    mma_bf16(acc[mt * NT + nt], aH[mt], bh);
                    mma_bf16(acc[mt * NT + nt], aH[mt], bl);
                    mma_bf16(acc[mt * NT + nt], aL[mt], bh);
                }
            }
        }
    }
}

/* 2xFP16 tile: A single fp16, B fp16 hi/lo */
template<int MT, int NT, int RB, int KC>
__device__ __forceinline__ void compute_tile_h(
    float acc[][4], uint32_t A, uint32_t Bh, uint32_t Bl,
    int wm, int wn, int lid)
{
    const int arow = lid & 15;
    const int ak   = (lid >> 4) * 16;
    const int brow = (lid & 7) + ((lid >> 4) & 1) * 8;
    const int bk   = ((lid >> 3) & 1) * 16;
#pragma unroll
    for (int kc = 0; kc < KC; ++kc) {
        uint32_t aH[MT][4];
#pragma unroll
        for (int mt = 0; mt < MT; ++mt) {
            uint32_t off = (uint32_t)(wm * (MT * 16) + mt * 16 + arow) * RB + kc * 32 + ak;
            LDMX4(aH[mt], A + off);
        }
#pragma unroll
        for (int np = 0; np < NT / 2; ++np) {
            uint32_t boff = (uint32_t)(wn * (NT * 8) + np * 16 + brow) * RB + kc * 32 + bk;
            uint32_t bH[4], bL[4];
            LDMX4(bH, Bh + boff);
            LDMX4(bL, Bl + boff);
#pragma unroll
            for (int half = 0; half < 2; ++half) {
                int nt = np * 2 + half;
#pragma unroll
                for (int mt = 0; mt < MT; ++mt) {
                    mma_fp16(acc[mt * NT + nt], aH[mt], bH + half * 2);
                    mma_fp16(acc[mt * NT + nt], aH[mt], bL + half * 2);
                }
            }
        }
    }
}

/* ============================================================
 * split_inputs / transpose_w  (prep)
 * ============================================================ */
__global__ __launch_bounds__(256) void split_inputs(
    const float* q, const float* k, const float* kg, const float* v,
    __nv_bfloat16* hi, __nv_bfloat16* lo)
{
    const float* S;
    if (blockIdx.y == 0) S = q; else if (blockIdx.y == 1) S = k;
    else if (blockIdx.y == 2) S = kg; else S = v;
    size_t off = (size_t)blockIdx.y * MROWS * EM;
    size_t i = (size_t)blockIdx.x * 256 + threadIdx.x;
    float4 x = ((const float4*)S)[i];
    uint32_t h0, l0, h1, l1;
    split2(x.x, x.y, h0, l0);
    split2(x.z, x.w, h1, l1);
    *(uint2*)(hi + off + i * 4) = make_uint2(h0, h1);
    *(uint2*)(lo + off + i * 4) = make_uint2(l0, l1);
}

__global__ __launch_bounds__(256) void transpose_w(
    const float* W0, const float* W1, const float* W2,
    const float* W3, const float* W4,
    __nv_bfloat16* outhi, __nv_bfloat16* outlo)
{
    const float* W;
    if (blockIdx.z == 0) W = W0; else if (blockIdx.z == 1) W = W1;
    else if (blockIdx.z == 2) W = W2; else if (blockIdx.z == 3) W = W3; else W = W4;
    size_t off = (size_t)blockIdx.z * EM * EM;
    __shared__ float t[32][33];
    int tx = threadIdx.x, ty = threadIdx.y;
    int x = blockIdx.x * 32 + tx;
    int y0 = blockIdx.y * 32;
    for (int i = ty; i < 32; i += 8)
        t[i][tx] = W[(size_t)(y0 + i) * EM + x];
    __syncthreads();
    int xo = blockIdx.y * 32 + tx;
    int yo0 = blockIdx.x * 32;
    for (int i = ty; i < 32; i += 8) {
        float val = t[tx][i];
        __nv_bfloat16 h = __float2bfloat16(val);
        float r = val - __bfloat162float(h);
        size_t idx = off + (size_t)(yo0 + i) * EM + xo;
        outhi[idx] = h;
        outlo[idx] = __float2bfloat16(r);
    }
}

/* ============================================================
 * proj_body: BM=64, BN=128, BK=32; 2-stage cp.async pipeline
 * stage: [Ah 5120][Al 5120][Bh 10240][Bl 10240] = 30720
 * mode 0: fp32 [m,n]; 1: bf16 hi/lo [bh,s,d] (scaled); 2: fp16 hi/lo [bh,d,s]
 * ============================================================ */
#define PJ_STGB 30720

__device__ __forceinline__ void proj_body(
    uint32_t* smw,
    const __nv_bfloat16* A1h, const __nv_bfloat16* A1l,
    const __nv_bfloat16* A2h, const __nv_bfloat16* A2l,
    const __nv_bfloat16* W1h, const __nv_bfloat16* W1l,
    const __nv_bfloat16* W2h, const __nv_bfloat16* W2l,
    const float* b1, const float* b2, float oscale,
    float* outf, void* outhi, void* outlo,
    int mode, int n0, int m0)
{
    const int tid = threadIdx.x, wid = tid >> 5, lid = tid & 31;
    const int wm = wid & 1, wn = wid >> 1, grp = lid >> 2, tig = lid & 3;
    const uint32_t smb = smem_u32(smw);
    const int LDB = EM * 2;

    float acc[8][4];
#pragma unroll
    for (int i = 0; i < 8; ++i)
#pragma unroll
        for (int j = 0; j < 4; ++j) acc[i][j] = 0.f;

    const int CPP = EM / 32;
    const int NCH = (A2h ? 2 : 1) * CPP;

    auto issue = [&](int slot, int c) {
        int pass = (c >= CPP);
        int k0b = (c - pass * CPP) * 64;
        const char* sAh = (const char*)(pass ? A2h : A1h) + (size_t)m0 * LDB;
        const char* sAl = (const char*)(pass ? A2l : A1l) + (size_t)m0 * LDB;
        const char* sWh = (const char*)(pass ? W2h : W1h) + (size_t)n0 * LDB;
        const char* sWl = (const char*)(pass ? W2l : W1l) + (size_t)n0 * LDB;
        uint32_t base = smb + (uint32_t)slot * PJ_STGB;
#pragma unroll
        for (int it = 0; it < 6; ++it) {
            int t = tid + it * 256;
            const char* sp;
            uint32_t doff;
            int row, seg;
            if (t < 512) {
                int buf = t >> 8, e = t & 255;
                row = e >> 2; seg = e & 3;
                sp = buf ? sAl : sAh;
                doff = (uint32_t)buf * 5120 + row * 80 + seg * 16;
            } else {
                int e = t - 512;
                int buf = e >> 9; e &= 511;
                row = e >> 2; seg = e & 3;
                sp = buf ? sWl : sWh;
                doff = 10240u + (uint32_t)buf * 10240 + row * 80 + seg * 16;
            }
            cp16(base + doff, sp + (size_t)row * LDB + k0b + seg * 16);
        }
    };

    issue(0, 0); CP_COMMIT();
    issue(1, 1); CP_COMMIT();
    for (int c = 0; c < NCH; ++c) {
        CP_WAIT1();
        __syncthreads();
        uint32_t cb = smb + (uint32_t)(c & 1) * PJ_STGB;
        compute_tile<2, 4, 80, 2>(acc, cb, cb + 5120, cb + 10240, cb + 20480,
                                  wm, wn, lid);
        __syncthreads();
        if (c + 2 < NCH) issue(c & 1, c + 2);
        CP_COMMIT();
    }

    float* Csm = (float*)smw;
    const int CS = 132;
#pragma unroll
    for (int mt = 0; mt < 2; ++mt)
#pragma unroll
        for (int nt = 0; nt < 4; ++nt) {
            int row = wm * 32 + mt * 16 + grp, col = wn * 32 + nt * 8 + tig * 2;
            float* a = acc[mt * 4 + nt];
            *(float2*)&Csm[row * CS + col]       = make_float2(a[0], a[1]);
            *(float2*)&Csm[(row + 8) * CS + col] = make_float2(a[2], a[3]);
        }
    __syncthreads();

    if (mode == 2) {
        int b = m0 >> 11, sbase = m0 & (SQ - 1);
#pragma unroll
        for (int it = 0; it < 8; ++it) {
            int e = tid + it * 256;
            int col = e >> 4, sb = e & 15;
            int nn = n0 + col;
            float bias = b1[nn];
            float4 v;
            v.x = Csm[(sb * 4 + 0) * CS + col] + bias;
            v.y = Csm[(sb * 4 + 1) * CS + col] + bias;
            v.z = Csm[(sb * 4 + 2) * CS + col] + bias;
            v.w = Csm[(sb * 4 + 3) * CS + col] + bias;
            int hh = nn >> 6, d = nn & 63;
            size_t idx = (((size_t)(b * NH + hh)) * DH + d) * SQ + sbase + sb * 4;
            uint32_t h0, l0, h1, l1;
            split2h(v.x, v.y, h0, l0);
            split2h(v.z, v.w, h1, l1);
            *(uint2*)((__half*)outhi + idx) = make_uint2(h0, h1);
            *(uint2*)((__half*)outlo + idx) = make_uint2(l0, l1);
        }
    } else {
#pragma unroll
        for (int it = 0; it < 8; ++it) {
            int e = tid + it * 256;
            int row = e >> 5, c4 = (e & 31) * 4;
            int m = m0 + row, n = n0 + c4;
            float4 v = *(float4*)&Csm[row * CS + c4];
            v.x += b1[n + 0]; v.y += b1[n + 1]; v.z += b1[n + 2]; v.w += b1[n + 3];
            if (b2) { v.x += b2[n + 0]; v.y += b2[n + 1]; v.z += b2[n + 2]; v.w += b2[n + 3]; }
            v.x *= oscale; v.y *= oscale; v.z *= oscale; v.w *= oscale;
            if (mode == 1) {
                int b = m >> 11, sA = m & (SQ - 1);
                int hh = n >> 6, d = n & 63;
                size_t idx = (((size_t)(b * NH + hh)) * SQ + sA) * DH + d;
                uint32_t h0, l0, h1, l1;
                split2(v.x, v.y, h0, l0);
                split2(v.z, v.w, h1, l1);
                *(uint2*)((__nv_bfloat16*)outhi + idx) = make_uint2(h0, h1);
                *(uint2*)((__nv_bfloat16*)outlo + idx) = make_uint2(l0, l1);
            } else {
                *(float4*)(outf + (size_t)m * EM + n) = v;
            }
        }
    }
}

__global__ __launch_bounds__(256, 3) void proj_qkv(
    const __nv_bfloat16* Ahi, const __nv_bfloat16* Alo,
    const __nv_bfloat16* Whi, const __nv_bfloat16* Wlo,
    const float* bq, const float* bk, const float* bkg, const float* bv,
    __nv_bfloat16* Qhi, __nv_bfloat16* Qlo,
    __nv_bfloat16* Khi, __nv_bfloat16* Klo,
    __half* Vthi, __half* Vtlo)
{
    extern __shared__ uint32_t smw[];
    const int n0 = blockIdx.x * 128, m0 = blockIdx.y * 64;
    const size_t AT = (size_t)MROWS * EM, WT = (size_t)EM * EM;
    if (blockIdx.z == 0)
        proj_body(smw, Ahi, Alo, nullptr, nullptr, Whi, Wlo, nullptr, nullptr,
                  bq, nullptr, 0.125f, nullptr, Qhi, Qlo, 1, n0, m0);
    else if (blockIdx.z == 1)
        proj_body(smw, Ahi + AT, Alo + AT, Ahi + 2*AT, Alo + 2*AT,
                  Whi + WT, Wlo + WT, Whi + 2*WT, Wlo + 2*WT,
                  bk, bkg, 1.0f, nullptr, Khi, Klo, 1, n0, m0);
    else
        proj_body(smw, Ahi + 3*AT, Alo + 3*AT, nullptr, nullptr,
                  Whi + 3*WT, Wlo + 3*WT, nullptr, nullptr,
                  bv, nullptr, 1.0f, nullptr, Vthi, Vtlo, 2, n0, m0);
}

__global__ __launch_bounds__(256, 3) void proj_o(
    const __nv_bfloat16* Ohi, const __nv_bfloat16* Olo,
    const __nv_bfloat16* Whi, const __nv_bfloat16* Wlo,
    const float* bo, float* C)
{
    extern __shared__ uint32_t smw[];
    const size_t WT = (size_t)EM * EM;
    proj_body(smw, Ohi, Olo, nullptr, nullptr, Whi + 4*WT, Wlo + 4*WT,
              nullptr, nullptr, bo, nullptr, 1.0f, C, nullptr, nullptr, 0,
              blockIdx.x * 128, blockIdx.y * 64);
}

/* ============================================================
 * qk_mma: BM=64, BN=128, K=64 single-shot (scale pre-folded into Q)
 * e = mask ? exp(score) : 0, stored fp16
 * smem: [Qh 9216][Ql 9216][Kh 18432][Kl 18432] = 55296
 * ============================================================ */
__global__ __launch_bounds__(256, 3) void qk_mma(
    const __nv_bfloat16* Qhi, const __nv_bfloat16* Qlo,
    const __nv_bfloat16* Khi, const __nv_bfloat16* Klo,
    const int* __restrict__ mask, __half* __restrict__ e_out,
    float* __restrict__ lp)
{
    extern __shared__ uint32_t smw[];
    const int tid = threadIdx.x, wid = tid >> 5, lid = tid & 31;
    const int n0 = blockIdx.x * 128, m0 = blockIdx.y * 64;
    const int bh = blockIdx.z, b = bh / NH;
    const int wm = wid & 1, wn = wid >> 1, grp = lid >> 2, tig = lid & 3;
    const uint32_t smb = smem_u32(smw);
    const char* sQh = (const char*)Qhi + ((size_t)bh * SQ + m0) * 128;
    const char* sQl = (const char*)Qlo + ((size_t)bh * SQ + m0) * 128;
    const char* sKh = (const char*)Khi + ((size_t)bh * SQ + n0) * 128;
    const char* sKl = (const char*)Klo + ((size_t)bh * SQ + n0) * 128;

#pragma unroll
    for (int it = 0; it < 12; ++it) {
        int t = tid + it * 256;
        const char* sp;
        uint32_t doff;
        int row, seg;
        if (t < 1024) {
            int buf = t >> 9, e = t & 511;
            row = e >> 3; seg = e & 7;
            sp = buf ? sQl : sQh;
            doff = (uint32_t)buf * 9216 + row * 144 + seg * 16;
        } else {
            int e = t - 1024;
            int buf = e >> 10; e &= 1023;
            row = e >> 3; seg = e & 7;
            sp = buf ? sKl : sKh;
            doff = 18432u + (uint32_t)buf * 18432 + row * 144 + seg * 16;
        }
        cp16(smb + doff, sp + (size_t)row * 128 + seg * 16);
    }
    CP_COMMIT();
    CP_WAIT0();
    __syncthreads();

    float acc[8][4];
#pragma unroll
    for (int i = 0; i < 8; ++i)
#pragma unroll
        for (int j = 0; j < 4; ++j) acc[i][j] = 0.f;

    compute_tile<2, 4, 144, 4>(acc, smb, smb + 9216, smb + 18432, smb + 36864,
                               wm, wn, lid);
    __syncthreads();

    float* Csm = (float*)smw;
    const int CS = 132;
#pragma unroll
    for (int mt = 0; mt < 2; ++mt)
#pragma unroll
        for (int nt = 0; nt < 4; ++nt) {
            int row = wm * 32 + mt * 16 + grp, col = wn * 32 + nt * 8 + tig * 2;
            float* a = acc[mt * 4 + nt];
            *(float2*)&Csm[row * CS + col]       = make_float2(a[0], a[1]);
            *(float2*)&Csm[(row + 8) * CS + col] = make_float2(a[2], a[3]);
        }
    __syncthreads();

    const int* mb = mask + (size_t)b * SQ * SQ;
    __half* eb = e_out + (size_t)bh * SQ * SQ;
#pragma unroll 1
    for (int it = 0; it < 8; ++it) {
        int eidx = tid + it * 256;
        int row = eidx >> 5, c4 = (eidx & 31) * 4;
        int m = m0 + row, n = n0 + c4;
        float4 v = *(float4*)&Csm[row * CS + c4];
        int4 mk = *(const int4*)(mb + (size_t)m * SQ + n);
        v.x = mk.x ? __expf(v.x) : 0.f;
        v.y = mk.y ? __expf(v.y) : 0.f;
        v.z = mk.z ? __expf(v.z) : 0.f;
        v.w = mk.w ? __expf(v.w) : 0.f;
        __half2 h0 = __floats2half2_rn(v.x, v.y);
        __half2 h1 = __floats2half2_rn(v.z, v.w);
        *(uint2*)(eb + (size_t)m * SQ + n) =
            make_uint2(*(uint32_t*)&h0, *(uint32_t*)&h1);
        float s4 = v.x + v.y + v.z + v.w;
#pragma unroll
        for (int o = 16; o; o >>= 1) s4 += __shfl_xor_sync(0xffffffffu, s4, o);
        if (lid == 0)
            lp[((size_t)bh * SQ + m) * 16 + blockIdx.x] = s4;
    }
}

/* ============================================================
 * av_mma: BM=64, BN=64; e fp16 cp.async direct to smem,
 * MMA on unnormalized e, acc scaled by 1/l at end;
 * attn = e*invl written from smem per chunk.
 * stage: [P 5120][Vh 5120][Vl 5120] = 15360; x2 + invl 256
 * ============================================================ */
#define AV_STGB 15360

__global__ __launch_bounds__(256, 4) void av_mma(
    const __half* __restrict__ e_in, const float* __restrict__ lp,
    const __half* Vhi, const __half* Vlo,
    float* __restrict__ attn, __nv_bfloat16* Ohi, __nv_bfloat16* Olo)
{
    extern __shared__ uint32_t smw[];
    const int tid = threadIdx.x, wid = tid >> 5, lid = tid & 31;
    const int m0 = blockIdx.x * 64;
    const int bh = blockIdx.y, b = bh / NH, hh = bh % NH;
    const int wm = wid & 1, wn = wid >> 1, grp = lid >> 2, tig = lid & 3;
    const uint32_t smb = smem_u32(smw);
    const char* Pb = (const char*)(e_in + (size_t)bh * SQ * SQ + (size_t)m0 * SQ);
    float* attnb = attn + (size_t)bh * SQ * SQ + (size_t)m0 * SQ;
    const char* Vh = (const char*)Vhi + (size_t)bh * DH * SQ * 2;
    const char* Vl = (const char*)Vlo + (size_t)bh * DH * SQ * 2;
    float* invl = (float*)((char*)smw + 2 * AV_STGB);

    if (tid < 64) {
        const float* q = lp + ((size_t)bh * SQ + m0 + tid) * 16;
        float s = 0.f;
#pragma unroll
        for (int i = 0; i < 16; ++i) s += q[i];
        invl[tid] = 1.f / fmaxf(s, 1e-30f);
    }
    __syncthreads();

    float acc[4][4];
#pragma unroll
    for (int i = 0; i < 4; ++i)
#pragma unroll
        for (int j = 0; j < 4; ++j) acc[i][j] = 0.f;

    /* cp.async one chunk: P 64x32 fp16 (256 x 16B), Vh/Vl 64x32 fp16 each */
    auto issue = [&](int slot, int c) {
        uint32_t base = smb + (uint32_t)slot * AV_STGB;
        int k0b = c * 64;   /* 32 halves = 64 bytes */
#pragma unroll
        for (int it = 0; it < 3; ++it) {
            int t = tid + it * 256;
            int sec = t >> 8, u = t & 255;
            int row = u >> 2, seg = u & 3;
            const char* sp = sec == 0 ? Pb : (sec == 1 ? Vh : Vl);
            cp16(base + (uint32_t)sec * 5120 + row * 80 + seg * 16,
                 sp + (size_t)row * (SQ * 2) + k0b + seg * 16);
        }
    };
    /* write attn = e * invl for chunk in smem slot */
    auto attn_write = [&](int slot, int k0) {
        char* H = (char*)smw + slot * AV_STGB;
#pragma unroll
        for (int p = 0; p < 2; ++p) {
            int i = tid + p * 256, r = i >> 3, c = i & 7;
            uint2 u = *(uint2*)(H + r * 80 + c * 8);
            __half2 h0 = *(__half2*)&u.x;
            __half2 h1 = *(__half2*)&u.y;
            float2 f0 = __half22float2(h0);
            float2 f1 = __half22float2(h1);
            float il = invl[r];
            float4 w = make_float4(f0.x * il, f0.y * il, f1.x * il, f1.y * il);
            *(float4*)(attnb + (size_t)r * SQ + k0 + c * 4) = w;
        }
    };

    issue(0, 0); CP_COMMIT();
    issue(1, 1); CP_COMMIT();
    const int NCH = SQ / 32;
    for (int c = 0; c < NCH; ++c) {
        CP_WAIT1();
        __syncthreads();
        uint32_t cb = smb + (uint32_t)(c & 1) * AV_STGB;
        attn_write(c & 1, c * 32);
        compute_tile_h<2, 2, 80, 2>(acc, cb, cb + 5120, cb + 10240,
                                    wm, wn, lid);
        __syncthreads();
        if (c + 2 < NCH) issue(c & 1, c + 2);
        CP_COMMIT();
    }

    float* Csm = (float*)smw;
    const int CS = 68;
#pragma unroll
    for (int mt = 0; mt < 2; ++mt)
#pragma unroll
        for (int nt = 0; nt < 2; ++nt) {
            int row = wm * 32 + mt * 16 + grp, col = wn * 16 + nt * 8 + tig * 2;
            float il0 = invl[row], il1 = invl[row + 8];
            float* a = acc[mt * 2 + nt];
            *(float2*)&Csm[row * CS + col]       = make_float2(a[0] * il0, a[1] * il0);
            *(float2*)&Csm[(row + 8) * CS + col] = make_float2(a[2] * il1, a[3] * il1);
        }
    __syncthreads();

#pragma unroll
    for (int it = 0; it < 4; ++it) {
        int e = tid + it * 256;
        int row = e >> 4, c4 = (e & 15) * 4;
        float4 v = *(float4*)&Csm[row * CS + c4];
        size_t idx = (size_t)(b * SQ + m0 + row) * EM + hh * DH + c4;
        uint32_t h0, l0, h1, l1;
        split2(v.x, v.y, h0, l0);
        split2(v.z, v.w, h1, l1);
        *(uint2*)(Ohi + idx) = make_uint2(h0, h1);
        *(uint2*)(Olo + idx) = make_uint2(l0, l1);
    }
}

/* ===================================================================== */
extern "C" void kernel_launch(void* const* d_in, const int* in_sizes, int n_in,
                              void* d_out, int out_size)
{
    (void)in_sizes; (void)n_in;
    const float* query = (const float*)d_in[0];
    const float* key   = (const float*)d_in[1];
    const float* value = (const float*)d_in[2];
    const float* kginf = (const float*)d_in[3];
    const int*   mask  = (const int*)d_in[4];
    const float* Wq  = (const float*)d_in[5];  const float* bq  = (const float*)d_in[6];
    const float* Wk  = (const float*)d_in[7];  const float* bk  = (const float*)d_in[8];
    const float* Wv  = (const float*)d_in[9];  const float* bv  = (const float*)d_in[10];
    const float* Wkg = (const float*)d_in[11]; const float* bkg = (const float*)d_in[12];
    const float* Wo  = (const float*)d_in[13]; const float* bo  = (const float*)d_in[14];

    __nv_bfloat16 *ahi, *alo, *whi, *wlo, *qhi, *qlo, *khi, *klo, *ohi, *olo;
    __half *vthi, *vtlo, *ge;
    float *glp, *gmain, *gattnf;
    cudaGetSymbolAddress((void**)&ahi,  g_Ahi);
    cudaGetSymbolAddress((void**)&alo,  g_Alo);
    cudaGetSymbolAddress((void**)&whi,  g_Wthi);
    cudaGetSymbolAddress((void**)&wlo,  g_Wtlo);
    cudaGetSymbolAddress((void**)&qhi,  g_Qhi);
    cudaGetSymbolAddress((void**)&qlo,  g_Qlo);
    cudaGetSymbolAddress((void**)&khi,  g_Khi);
    cudaGetSymbolAddress((void**)&klo,  g_Klo);
    cudaGetSymbolAddress((void**)&vthi, g_Vthi);
    cudaGetSymbolAddress((void**)&vtlo, g_Vtlo);
    cudaGetSymbolAddress((void**)&ohi,  g_Ohi);
    cudaGetSymbolAddress((void**)&olo,  g_Olo);
    cudaGetSymbolAddress((void**)&ge,   g_e);
    cudaGetSymbolAddress((void**)&glp,  g_lp);
    cudaGetSymbolAddress((void**)&gmain, g_main);
    cudaGetSymbolAddress((void**)&gattnf, g_attnf);

    const long long MAIN = (long long)MROWS * EM;
    const long long ATTN = (long long)NBH * SQ * SQ;
    float* out = (float*)d_out;
    float* main_out;
    float* attn;
    long long osz = (long long)out_size;
    if (osz >= MAIN + ATTN)      { main_out = out; attn = out + MAIN; }
    else if (osz >= ATTN)        { attn = out; main_out = gmain; }
    else                         { main_out = out; attn = gattnf; }

    const int PJ_SMEM = 2 * PJ_STGB;           /* 61440 */
    const int QK_SMEM = 55296;
    const int AV_SMEM = 2 * AV_STGB + 256;     /* 30976 */
    cudaFuncSetAttribute(proj_qkv, cudaFuncAttributeMaxDynamicSharedMemorySize, PJ_SMEM);
    cudaFuncSetAttribute(proj_o,   cudaFuncAttributeMaxDynamicSharedMemorySize, PJ_SMEM);
    cudaFuncSetAttribute(qk_mma,   cudaFuncAttributeMaxDynamicSharedMemorySize, QK_SMEM);
    cudaFuncSetAttribute(av_mma,   cudaFuncAttributeMaxDynamicSharedMemorySize, AV_SMEM);

    dim3 blk(256);
    split_inputs<<<dim3(MROWS * EM / 4 / 256, 4), blk>>>(query, key, kginf, value, ahi, alo);
    transpose_w<<<dim3(EM/32, EM/32, 5), dim3(32, 8)>>>(Wq, Wk, Wkg, Wv, Wo, whi, wlo);

    proj_qkv<<<dim3(EM/128, MROWS/64, 3), blk, PJ_SMEM>>>(
        ahi, alo, whi, wlo, bq, bk, bkg, bv, qhi, qlo, khi, klo, vthi, vtlo);

    qk_mma<<<dim3(SQ/128, SQ/64, NBH), blk, QK_SMEM>>>(
        qhi, qlo, khi, klo, mask, ge, glp);

    av_mma<<<dim3(SQ/64, NBH), blk, AV_SMEM>>>(
        ge, glp, vthi, vtlo, attn, ohi, olo);

    proj_o<<<dim3(EM/128, MROWS/64), blk, PJ_SMEM>>>(ohi, olo, whi, wlo, bo, main_out);
}